// round 2
// baseline (speedup 1.0000x reference)
#include <cuda_runtime.h>
#include <cstdint>

#define NB    16
#define CIN   256
#define COUT  128
#define VRAW  10242
#define NVERT 40962

// Scratch (static __device__ — no allocation in kernel_launch)
__device__ float g_h[(size_t)NB * COUT * VRAW];   // 83.9 MB: h = W@x + b
__device__ int   g_nd[VRAW * 8];                  // 328 KB: nd[v][k] = up[down[v]][k]

// ---------------------------------------------------------------------------
// Kernel 1: fold up_neigh[down[v]][k] into an int32 table (L2-resident later)
// NOTE: harness materializes int64 reference inputs as int32 buffers.
// ---------------------------------------------------------------------------
__global__ void prep_nd_kernel(const int* __restrict__ up,
                               const int* __restrict__ down)
{
    int i = blockIdx.x * blockDim.x + threadIdx.x;
    if (i >= VRAW * 8) return;
    int v = i >> 3, k = i & 7;
    int val = 0;
    if (k < 7) {
        int d = down[v];
        val = up[d * 7 + k];
    }
    g_nd[i] = val;
}

// ---------------------------------------------------------------------------
// Kernel 2: GEMM  h[b,o,v] = sum_c W[o,c] * x[b,c,v] + bias[o]
// fp32 via packed fma.rn.f32x2 (FFMA2: 2 FMAs/lane/instr on sm_103a)
// Tile: 128(o) x 128(v), BK=16, 256 threads, 8x8 outputs/thread (4 v-pairs)
// ---------------------------------------------------------------------------
__device__ __forceinline__ unsigned long long dup2(float a) {
    unsigned long long r;
    asm("mov.b64 %0, {%1, %1};" : "=l"(r) : "f"(a));
    return r;
}
__device__ __forceinline__ void ffma2(unsigned long long& d,
                                      unsigned long long a,
                                      unsigned long long b) {
    asm("fma.rn.f32x2 %0, %1, %2, %0;" : "+l"(d) : "l"(a), "l"(b));
}

#define BK 16
#define BN 128

__global__ __launch_bounds__(256, 2) void gemm_kernel(
    const float* __restrict__ x, const float* __restrict__ W,
    const float* __restrict__ bias)
{
    __shared__ float sW[2][BK][COUT];   // [k][o], transposed on store
    __shared__ float sX[2][BK][BN];     // [k][v]

    int b   = blockIdx.y;
    int v0  = blockIdx.x * BN;
    int tid = threadIdx.x;
    const float* xb = x + (size_t)b * CIN * VRAW;

    int ty = tid >> 4, tx = tid & 15;
    int oT = ty * 8;         // this thread's 8 output rows (o)
    int vT = tx * 8;         // this thread's 8 output cols (v), as 4 f32x2 pairs

    unsigned long long acc[8][4];
    #pragma unroll
    for (int i = 0; i < 8; i++)
        #pragma unroll
        for (int p = 0; p < 4; p++) acc[i][p] = 0ULL;

    // prologue: stage 0
    #pragma unroll
    for (int i = 0; i < 8; i++) {
        int e = tid + i * 256;
        sW[0][e & 15][e >> 4] = W[(e >> 4) * CIN + (e & 15)];
    }
    #pragma unroll
    for (int i = 0; i < 8; i++) {
        int e = tid + i * 256;
        int c = e >> 7, v = e & 127;
        int gv = v0 + v;
        sX[0][c][v] = (gv < VRAW) ? xb[(size_t)c * VRAW + gv] : 0.f;
    }
    __syncthreads();

    const int NK = CIN / BK;  // 16 k-chunks
    for (int kt = 0; kt < NK; kt++) {
        int buf = kt & 1;
        if (kt + 1 < NK) {
            int kc = (kt + 1) * BK;
            #pragma unroll
            for (int i = 0; i < 8; i++) {
                int e = tid + i * 256;
                sW[buf ^ 1][e & 15][e >> 4] = W[(e >> 4) * CIN + kc + (e & 15)];
            }
            #pragma unroll
            for (int i = 0; i < 8; i++) {
                int e = tid + i * 256;
                int c = e >> 7, v = e & 127;
                int gv = v0 + v;
                sX[buf ^ 1][c][v] = (gv < VRAW) ? xb[(size_t)(kc + c) * VRAW + gv] : 0.f;
            }
        }
        #pragma unroll
        for (int k = 0; k < BK; k++) {
            const float4* wr = (const float4*)&sW[buf][k][oT];
            float4 w0 = wr[0], w1 = wr[1];
            unsigned long long wd[8];
            wd[0] = dup2(w0.x); wd[1] = dup2(w0.y);
            wd[2] = dup2(w0.z); wd[3] = dup2(w0.w);
            wd[4] = dup2(w1.x); wd[5] = dup2(w1.y);
            wd[6] = dup2(w1.z); wd[7] = dup2(w1.w);
            const unsigned long long* xr =
                (const unsigned long long*)&sX[buf][k][vT];
            unsigned long long xp[4];
            xp[0] = xr[0]; xp[1] = xr[1]; xp[2] = xr[2]; xp[3] = xr[3];
            #pragma unroll
            for (int i = 0; i < 8; i++)
                #pragma unroll
                for (int p = 0; p < 4; p++)
                    ffma2(acc[i][p], wd[i], xp[p]);
        }
        __syncthreads();
    }

    // epilogue: add bias, store as float2 (pairs are even-aligned, never split)
    #pragma unroll
    for (int i = 0; i < 8; i++) {
        int o = oT + i;
        float bo = __ldg(&bias[o]);
        float* hp = g_h + ((size_t)b * COUT + o) * VRAW;
        #pragma unroll
        for (int p = 0; p < 4; p++) {
            int gv = v0 + vT + p * 2;
            if (gv < VRAW) {
                float lo, hi;
                asm("mov.b64 {%0, %1}, %2;" : "=f"(lo), "=f"(hi) : "l"(acc[i][p]));
                *(float2*)&hp[gv] = make_float2(lo + bo, hi + bo);
            }
        }
    }
}

// ---------------------------------------------------------------------------
// Kernel 3: per-row scatter with last-write-wins (max v) duplicate semantics.
// One block per (b,o) row. winner[vert] = max v via shared atomicMax, then
// stream the full output row (no global memset of y, no global atomics).
// ---------------------------------------------------------------------------
__global__ __launch_bounds__(1024, 1) void scatter_kernel(
    const int* __restrict__ mpi, float* __restrict__ y)
{
    extern __shared__ int win[];      // NVERT ints = 160.0 KB
    int row = blockIdx.x;             // b*COUT + o
    int tid = threadIdx.x;

    for (int j = tid; j < NVERT; j += 1024) win[j] = -1;
    __syncthreads();

    const int* mrow = mpi + (size_t)row * VRAW;
    #pragma unroll
    for (int i = 0; i < 11; i++) {
        int v = tid + (i << 10);
        if (v < VRAW) {
            int k = __ldg(&mrow[v]);               // value in [0,7)
            int vert = g_nd[(v << 3) + k];         // L2-resident table
            atomicMax(&win[vert], v);              // last write (max v) wins
        }
    }
    __syncthreads();

    const float* hrow = g_h + (size_t)row * VRAW;
    float* yrow = y + (size_t)row * NVERT;
    for (int j = tid; j < NVERT; j += 1024) {
        int w = win[j];
        yrow[j] = (w >= 0) ? __ldg(&hrow[w]) : 0.f;  // gather hits L1/L2 (41KB row)
    }
}

// ---------------------------------------------------------------------------
extern "C" void kernel_launch(void* const* d_in, const int* in_sizes, int n_in,
                              void* d_out, int out_size)
{
    const float* x    = (const float*)d_in[0];
    const float* W    = (const float*)d_in[1];
    const float* bias = (const float*)d_in[2];
    const int*   up   = (const int*)d_in[3];
    const int*   down = (const int*)d_in[4];
    const int*   mpi  = (const int*)d_in[5];
    float* y = (float*)d_out;

    // idempotent, cheap; needed for 160KB dynamic smem
    cudaFuncSetAttribute(scatter_kernel,
                         cudaFuncAttributeMaxDynamicSharedMemorySize,
                         NVERT * (int)sizeof(int));

    prep_nd_kernel<<<(VRAW * 8 + 255) / 256, 256>>>(up, down);

    dim3 g((VRAW + BN - 1) / BN, NB);   // 81 x 16
    gemm_kernel<<<g, 256>>>(x, W, bias);

    scatter_kernel<<<NB * COUT, 1024, NVERT * (int)sizeof(int)>>>(mpi, y);
}

// round 4
// speedup vs baseline: 1.5150x; 1.5150x over previous
#include <cuda_runtime.h>
#include <cuda_bf16.h>
#include <cstdint>

#define NB    16
#define CIN   256
#define COUT  128
#define VRAW  10242
#define NVERT 40962

#define BM    128
#define BNV   128
#define BK    32
#define NKCH  (CIN / BK)                  // 8
#define NVB   ((VRAW + BNV - 1) / BNV)    // 81

// Scratch (static __device__ — no allocation in kernel_launch)
__device__ float g_h[(size_t)NB * COUT * VRAW];   // 83.9 MB
__device__ int   g_nd[VRAW * 8];                  // 328 KB

// ---------------- smem layout (bytes) ----------------
#define A_STRIDE 80            // 32 k * 2B + 16B pad (conflict-free ldmatrix)
#define B_STRIDE 272           // 128 v * 2B + 16B pad
#define A_TILE   (BM * A_STRIDE)   // 10240
#define B_TILE   (BK * B_STRIDE)   // 8704
#define OFF_A    0
#define OFF_B    (4 * A_TILE)      // 40960  (2 bufs x 2 splits)
#define SMEM_TOTAL (OFF_B + 4 * B_TILE)  // 75776

// ---------------------------------------------------------------------------
__device__ __forceinline__ uint32_t smem_u32(const void* p) {
    uint32_t a;
    asm("{ .reg .u64 t; cvta.to.shared.u64 t, %1; cvt.u32.u64 %0, t; }"
        : "=r"(a) : "l"(p));
    return a;
}

__device__ __forceinline__ void ldsm4(uint32_t* r, uint32_t addr) {
    asm volatile("ldmatrix.sync.aligned.m8n8.x4.shared.b16 {%0,%1,%2,%3}, [%4];"
                 : "=r"(r[0]), "=r"(r[1]), "=r"(r[2]), "=r"(r[3]) : "r"(addr));
}
__device__ __forceinline__ void ldsm4t(uint32_t* r, uint32_t addr) {
    asm volatile("ldmatrix.sync.aligned.m8n8.x4.trans.shared.b16 {%0,%1,%2,%3}, [%4];"
                 : "=r"(r[0]), "=r"(r[1]), "=r"(r[2]), "=r"(r[3]) : "r"(addr));
}
__device__ __forceinline__ void mma_bf16(float* c, const uint32_t* a,
                                         uint32_t b0, uint32_t b1) {
    asm volatile(
        "mma.sync.aligned.m16n8k16.row.col.f32.bf16.bf16.f32 "
        "{%0,%1,%2,%3}, {%4,%5,%6,%7}, {%8,%9}, {%0,%1,%2,%3};"
        : "+f"(c[0]), "+f"(c[1]), "+f"(c[2]), "+f"(c[3])
        : "r"(a[0]), "r"(a[1]), "r"(a[2]), "r"(a[3]), "r"(b0), "r"(b1));
}

// two-term bf16 split of a float pair, packed as bf16x2 words
__device__ __forceinline__ void split2(float a, float b, uint32_t& hi, uint32_t& lo) {
    __nv_bfloat16 ah = __float2bfloat16(a), bh = __float2bfloat16(b);
    float ar = a - __bfloat162float(ah), br = b - __bfloat162float(bh);
    __nv_bfloat16 al = __float2bfloat16(ar), bl = __float2bfloat16(br);
    hi = (uint32_t)__bfloat16_as_ushort(ah) | ((uint32_t)__bfloat16_as_ushort(bh) << 16);
    lo = (uint32_t)__bfloat16_as_ushort(al) | ((uint32_t)__bfloat16_as_ushort(bl) << 16);
}

// ---------------------------------------------------------------------------
// Kernel 1: fold up_neigh[down[v]][k] into an int32 table
// ---------------------------------------------------------------------------
__global__ void prep_nd_kernel(const int* __restrict__ up,
                               const int* __restrict__ down)
{
    int i = blockIdx.x * blockDim.x + threadIdx.x;
    if (i >= VRAW * 8) return;
    int v = i >> 3, k = i & 7;
    int val = 0;
    if (k < 7) val = up[down[v] * 7 + k];
    g_nd[i] = val;
}

// ---------------------------------------------------------------------------
// Kernel 2: HMMA GEMM  h[b,o,v] = sum_c W[o,c]*x[b,c,v] + bias[o]
// bf16 two-term split via mma.sync.m16n8k16 (portable PTX, tensor pipe)
// CTA 128x128, BK=32, 8 warps (2x4), warp tile 64x32, double-buffered smem.
// ---------------------------------------------------------------------------
__global__ __launch_bounds__(256, 2)
void gemm_mma_kernel(const float* __restrict__ x, const float* __restrict__ W,
                     const float* __restrict__ bias)
{
    extern __shared__ char smem[];
    const uint32_t sbase = smem_u32(smem);
    const int tid  = threadIdx.x;
    const int lane = tid & 31;
    const int wid  = tid >> 5;
    const int b    = blockIdx.y;
    const int v0   = blockIdx.x * BNV;
    const int wo   = (wid >> 2) * 64;   // warp o-base (0 / 64)
    const int wv   = (wid & 3) * 32;    // warp v-base (0/32/64/96)

    float acc[4][4][4];
    #pragma unroll
    for (int i = 0; i < 4; i++)
        #pragma unroll
        for (int j = 0; j < 4; j++)
            #pragma unroll
            for (int e = 0; e < 4; e++) acc[i][j][e] = 0.f;

    // ---- staging helpers ----
    // A (W): 128o x 32c -> bf16 hi/lo, row stride 80B
    auto stageA = [&](int kc, int buf) {
        int o = tid >> 1, half = tid & 1;
        const float* wr = W + o * CIN + kc + half * 16;
        char* Ah = smem + OFF_A + (buf * 2 + 0) * A_TILE + o * A_STRIDE + half * 32;
        char* Al = smem + OFF_A + (buf * 2 + 1) * A_TILE + o * A_STRIDE + half * 32;
        #pragma unroll
        for (int g = 0; g < 2; g++) {
            float4 f0 = *(const float4*)(wr + g * 8);
            float4 f1 = *(const float4*)(wr + g * 8 + 4);
            uint4 hi, lo;
            split2(f0.x, f0.y, hi.x, lo.x);
            split2(f0.z, f0.w, hi.y, lo.y);
            split2(f1.x, f1.y, hi.z, lo.z);
            split2(f1.z, f1.w, hi.w, lo.w);
            *(uint4*)(Ah + g * 16) = hi;
            *(uint4*)(Al + g * 16) = lo;
        }
    };
    // B (x): 32c x 128v, scalar loads (x rows only 8B-aligned)
    auto loadB = [&](int kc, float* f) {
        int r = tid >> 3, seg = tid & 7;
        const float* xp = x + ((size_t)b * CIN + kc + r) * VRAW + v0 + seg * 16;
        int rem = VRAW - (v0 + seg * 16);
        #pragma unroll
        for (int j = 0; j < 16; j++) f[j] = (j < rem) ? xp[j] : 0.f;
    };
    auto storeB = [&](const float* f, int buf) {
        int r = tid >> 3, seg = tid & 7;
        char* Bh = smem + OFF_B + (buf * 2 + 0) * B_TILE + r * B_STRIDE + seg * 32;
        char* Bl = smem + OFF_B + (buf * 2 + 1) * B_TILE + r * B_STRIDE + seg * 32;
        #pragma unroll
        for (int g = 0; g < 2; g++) {
            uint4 hi, lo;
            split2(f[g * 8 + 0], f[g * 8 + 1], hi.x, lo.x);
            split2(f[g * 8 + 2], f[g * 8 + 3], hi.y, lo.y);
            split2(f[g * 8 + 4], f[g * 8 + 5], hi.z, lo.z);
            split2(f[g * 8 + 6], f[g * 8 + 7], hi.w, lo.w);
            *(uint4*)(Bh + g * 16) = hi;
            *(uint4*)(Bl + g * 16) = lo;
        }
    };

    // ---- compute one BK=32 chunk from smem[buf] ----
    const int arow   = lane & 15;
    const int acol16 = (lane >> 4) * 16;
    const int brow   = ((lane >> 3) & 1) * 8 + (lane & 7);
    const int bcol16 = (lane >> 4) * 16;

    auto compute = [&](int buf) {
        #pragma unroll
        for (int combo = 0; combo < 3; combo++) {
            int sa = combo >> 1;   // 0,0,1
            int sx = combo & 1;    // 0,1,0
            uint32_t abase = sbase + OFF_A + (buf * 2 + sa) * A_TILE
                           + (wo + arow) * A_STRIDE + acol16;
            uint32_t bbase = sbase + OFF_B + (buf * 2 + sx) * B_TILE
                           + brow * B_STRIDE + wv * 2 + bcol16;
            #pragma unroll
            for (int ks = 0; ks < 2; ks++) {
                uint32_t af[4][4];
                #pragma unroll
                for (int mi = 0; mi < 4; mi++)
                    ldsm4(af[mi], abase + mi * 16 * A_STRIDE + ks * 32);
                uint32_t bf[2][4];
                #pragma unroll
                for (int np = 0; np < 2; np++)
                    ldsm4t(bf[np], bbase + ks * 16 * B_STRIDE + np * 32);
                #pragma unroll
                for (int mi = 0; mi < 4; mi++)
                    #pragma unroll
                    for (int nj = 0; nj < 4; nj++)
                        mma_bf16(acc[mi][nj], af[mi],
                                 bf[nj >> 1][(nj & 1) * 2],
                                 bf[nj >> 1][(nj & 1) * 2 + 1]);
            }
        }
    };

    // ---- pipeline ----
    float breg[16];
    stageA(0, 0);
    loadB(0, breg);
    storeB(breg, 0);
    __syncthreads();

    for (int kt = 0; kt < NKCH; kt++) {
        int buf = kt & 1;
        if (kt + 1 < NKCH) {
            loadB((kt + 1) * BK, breg);   // issue DRAM loads early
            stageA((kt + 1) * BK, buf ^ 1);
        }
        compute(buf);
        if (kt + 1 < NKCH) storeB(breg, buf ^ 1);
        __syncthreads();
    }

    // ---- epilogue: acc + bias -> g_h ----
    #pragma unroll
    for (int mi = 0; mi < 4; mi++) {
        int o0 = wo + mi * 16 + (lane >> 2);
        float b0 = __ldg(&bias[o0]);
        float b1 = __ldg(&bias[o0 + 8]);
        float* h0 = g_h + ((size_t)b * COUT + o0) * VRAW;
        float* h1 = h0 + (size_t)8 * VRAW;
        #pragma unroll
        for (int nj = 0; nj < 4; nj++) {
            int gv = v0 + wv + nj * 8 + (lane & 3) * 2;
            if (gv < VRAW) {
                *(float2*)(h0 + gv) = make_float2(acc[mi][nj][0] + b0,
                                                  acc[mi][nj][1] + b0);
                *(float2*)(h1 + gv) = make_float2(acc[mi][nj][2] + b1,
                                                  acc[mi][nj][3] + b1);
            }
        }
    }
}

// ---------------------------------------------------------------------------
// Kernel 3: per-row scatter with last-write-wins (max v) duplicate semantics.
// ---------------------------------------------------------------------------
__global__ __launch_bounds__(1024, 1) void scatter_kernel(
    const int* __restrict__ mpi, float* __restrict__ y)
{
    extern __shared__ int win[];      // NVERT ints = 160.0 KB
    int row = blockIdx.x;             // b*COUT + o
    int tid = threadIdx.x;

    for (int j = tid; j < NVERT; j += 1024) win[j] = -1;
    __syncthreads();

    const int* mrow = mpi + (size_t)row * VRAW;
    #pragma unroll
    for (int i = 0; i < 11; i++) {
        int v = tid + (i << 10);
        if (v < VRAW) {
            int k = __ldg(&mrow[v]);               // value in [0,7)
            int vert = g_nd[(v << 3) + k];         // L2-resident table
            atomicMax(&win[vert], v);              // last write (max v) wins
        }
    }
    __syncthreads();

    const float* hrow = g_h + (size_t)row * VRAW;
    float* yrow = y + (size_t)row * NVERT;
    for (int j = tid; j < NVERT; j += 1024) {
        int w = win[j];
        yrow[j] = (w >= 0) ? __ldg(&hrow[w]) : 0.f;
    }
}

// ---------------------------------------------------------------------------
extern "C" void kernel_launch(void* const* d_in, const int* in_sizes, int n_in,
                              void* d_out, int out_size)
{
    const float* x    = (const float*)d_in[0];
    const float* W    = (const float*)d_in[1];
    const float* bias = (const float*)d_in[2];
    const int*   up   = (const int*)d_in[3];
    const int*   down = (const int*)d_in[4];
    const int*   mpi  = (const int*)d_in[5];
    float* y = (float*)d_out;

    cudaFuncSetAttribute(scatter_kernel,
                         cudaFuncAttributeMaxDynamicSharedMemorySize,
                         NVERT * (int)sizeof(int));
    cudaFuncSetAttribute(gemm_mma_kernel,
                         cudaFuncAttributeMaxDynamicSharedMemorySize,
                         SMEM_TOTAL);

    prep_nd_kernel<<<(VRAW * 8 + 255) / 256, 256>>>(up, down);

    dim3 g(NVB, NB);   // 81 x 16
    gemm_mma_kernel<<<g, 256, SMEM_TOTAL>>>(x, W, bias);

    scatter_kernel<<<NB * COUT, 1024, NVERT * (int)sizeof(int)>>>(mpi, y);
}

// round 5
// speedup vs baseline: 1.5660x; 1.0336x over previous
#include <cuda_runtime.h>
#include <cuda_bf16.h>
#include <cstdint>

#define NB    16
#define CIN   256
#define COUT  128
#define VRAW  10242
#define VPAD  10248                       // mult of 8 -> 16B-aligned bf16 rows
#define NVERT 40962

#define BM    128
#define BNV   128
#define BK    32
#define NKCH  (CIN / BK)                  // 8
#define NVB   ((VRAW + BNV - 1) / BNV)    // 81

// Scratch (static __device__ — no allocation in kernel_launch)
__device__ float g_h[(size_t)NB * COUT * VRAW];                 // 83.9 MB
__device__ int   g_nd[VRAW * 8];                                // 328 KB
__device__ __nv_bfloat16 g_xh[(size_t)NB * CIN * VPAD + 4096];  // 84 MB (+slack)
__device__ __nv_bfloat16 g_xl[(size_t)NB * CIN * VPAD + 4096];  // 84 MB
__device__ __nv_bfloat16 g_Wh[COUT * CIN];
__device__ __nv_bfloat16 g_Wl[COUT * CIN];

// ---------------- smem layout (bytes) ----------------
#define A_STRIDE 80                // 32 k * 2B + 16B pad (conflict-free ldmatrix)
#define B_STRIDE 272               // 128 v * 2B + 16B pad
#define A_TILE   (BM * A_STRIDE)   // 10240
#define B_TILE   (BK * B_STRIDE)   // 8704
#define OFF_A    0
#define OFF_B    (4 * A_TILE)      // 40960  (2 bufs x 2 splits)
#define SMEM_TOTAL (OFF_B + 4 * B_TILE)  // 75776

// ---------------------------------------------------------------------------
__device__ __forceinline__ uint32_t smem_u32(const void* p) {
    uint32_t a;
    asm("{ .reg .u64 t; cvta.to.shared.u64 t, %1; cvt.u32.u64 %0, t; }"
        : "=r"(a) : "l"(p));
    return a;
}
__device__ __forceinline__ void cpa16(uint32_t dst, const void* src) {
    asm volatile("cp.async.cg.shared.global [%0], [%1], 16;"
                 :: "r"(dst), "l"(src) : "memory");
}
#define CP_COMMIT() asm volatile("cp.async.commit_group;" ::: "memory")
#define CP_WAIT(N)  asm volatile("cp.async.wait_group %0;" :: "n"(N) : "memory")

__device__ __forceinline__ void ldsm4(uint32_t* r, uint32_t addr) {
    asm volatile("ldmatrix.sync.aligned.m8n8.x4.shared.b16 {%0,%1,%2,%3}, [%4];"
                 : "=r"(r[0]), "=r"(r[1]), "=r"(r[2]), "=r"(r[3]) : "r"(addr));
}
__device__ __forceinline__ void ldsm4t(uint32_t* r, uint32_t addr) {
    asm volatile("ldmatrix.sync.aligned.m8n8.x4.trans.shared.b16 {%0,%1,%2,%3}, [%4];"
                 : "=r"(r[0]), "=r"(r[1]), "=r"(r[2]), "=r"(r[3]) : "r"(addr));
}
__device__ __forceinline__ void mma_bf16(float* c, const uint32_t* a,
                                         uint32_t b0, uint32_t b1) {
    asm volatile(
        "mma.sync.aligned.m16n8k16.row.col.f32.bf16.bf16.f32 "
        "{%0,%1,%2,%3}, {%4,%5,%6,%7}, {%8,%9}, {%0,%1,%2,%3};"
        : "+f"(c[0]), "+f"(c[1]), "+f"(c[2]), "+f"(c[3])
        : "r"(a[0]), "r"(a[1]), "r"(a[2]), "r"(a[3]), "r"(b0), "r"(b1));
}

// ---- cheap two-term split: hi = truncate-to-bf16 (bit mask), lo = rn(a - hi)
__device__ __forceinline__ uint32_t pack_hi(float a, float b) {
    uint32_t r;
    asm("prmt.b32 %0, %1, %2, 0x7632;"
        : "=r"(r) : "r"(__float_as_uint(a)), "r"(__float_as_uint(b)));
    return r;   // low16 = hi(a), high16 = hi(b)
}
__device__ __forceinline__ float hi_f(float a) {
    return __uint_as_float(__float_as_uint(a) & 0xFFFF0000u);
}
__device__ __forceinline__ uint32_t pack_lo(float a, float b) {
    float la = a - hi_f(a), lb = b - hi_f(b);
    uint32_t r;
    asm("cvt.rn.bf16x2.f32 %0, %1, %2;" : "=r"(r) : "f"(lb), "f"(la));
    return r;   // low16 = lo(a), high16 = lo(b)
}

// ---------------------------------------------------------------------------
// Kernel 0a: split x (fp32) -> g_xh/g_xl (bf16, VPAD stride)
// ---------------------------------------------------------------------------
#define NSEG (VPAD / 8)   // 1281
__global__ __launch_bounds__(256) void convert_x_kernel(const float* __restrict__ x)
{
    int t = blockIdx.x * 256 + threadIdx.x;
    if (t >= NB * CIN * NSEG) return;
    int r = t / NSEG, s = t % NSEG;
    const float* src = x + (size_t)r * VRAW + s * 8;
    int valid = VRAW - s * 8;            // >= 8 except last seg (=2)
    float f[8];
    #pragma unroll
    for (int j = 0; j < 8; j += 2) {
        if (j + 1 < valid) { float2 v = *(const float2*)(src + j); f[j] = v.x; f[j+1] = v.y; }
        else               { f[j] = 0.f; f[j+1] = 0.f; }
    }
    uint4 hi, lo;
    hi.x = pack_hi(f[0], f[1]); lo.x = pack_lo(f[0], f[1]);
    hi.y = pack_hi(f[2], f[3]); lo.y = pack_lo(f[2], f[3]);
    hi.z = pack_hi(f[4], f[5]); lo.z = pack_lo(f[4], f[5]);
    hi.w = pack_hi(f[6], f[7]); lo.w = pack_lo(f[6], f[7]);
    size_t off = (size_t)r * VPAD + s * 8;
    *(uint4*)(g_xh + off) = hi;
    *(uint4*)(g_xl + off) = lo;
}

// ---------------------------------------------------------------------------
// Kernel 0b: split W -> g_Wh/g_Wl
// ---------------------------------------------------------------------------
__global__ __launch_bounds__(256) void convert_w_kernel(const float* __restrict__ W)
{
    int t = blockIdx.x * 256 + threadIdx.x;
    if (t >= COUT * CIN / 8) return;
    const float4* src = (const float4*)W + t * 2;
    float4 f0 = src[0], f1 = src[1];
    uint4 hi, lo;
    hi.x = pack_hi(f0.x, f0.y); lo.x = pack_lo(f0.x, f0.y);
    hi.y = pack_hi(f0.z, f0.w); lo.y = pack_lo(f0.z, f0.w);
    hi.z = pack_hi(f1.x, f1.y); lo.z = pack_lo(f1.x, f1.y);
    hi.w = pack_hi(f1.z, f1.w); lo.w = pack_lo(f1.z, f1.w);
    *(uint4*)(g_Wh + t * 8) = hi;
    *(uint4*)(g_Wl + t * 8) = lo;
}

// ---------------------------------------------------------------------------
// Kernel 1: fold up_neigh[down[v]][k] into an int32 table
// ---------------------------------------------------------------------------
__global__ void prep_nd_kernel(const int* __restrict__ up,
                               const int* __restrict__ down)
{
    int i = blockIdx.x * blockDim.x + threadIdx.x;
    if (i >= VRAW * 8) return;
    int v = i >> 3, k = i & 7;
    int val = 0;
    if (k < 7) val = up[down[v] * 7 + k];
    g_nd[i] = val;
}

// ---------------------------------------------------------------------------
// Kernel 2: HMMA GEMM on pre-split bf16, cp.async double-buffered staging.
// CTA 128x128, BK=32, 8 warps (2x4), warp tile 64x32.
// ---------------------------------------------------------------------------
__global__ __launch_bounds__(256, 2)
void gemm_mma_kernel(const float* __restrict__ bias)
{
    extern __shared__ char smem[];
    const uint32_t sbase = smem_u32(smem);
    const int tid  = threadIdx.x;
    const int lane = tid & 31;
    const int wid  = tid >> 5;
    const int b    = blockIdx.y;
    const int v0   = blockIdx.x * BNV;
    const int wo   = (wid >> 2) * 64;
    const int wv   = (wid & 3) * 32;

    float acc[4][4][4];
    #pragma unroll
    for (int i = 0; i < 4; i++)
        #pragma unroll
        for (int j = 0; j < 4; j++)
            #pragma unroll
            for (int e = 0; e < 4; e++) acc[i][j][e] = 0.f;

    // ---- async staging: pure copies of pre-split bf16 ----
    auto issueA = [&](int kc, int buf) {
        int o = tid >> 1, half = tid & 1;
        const __nv_bfloat16* sh = g_Wh + o * CIN + kc + half * 16;
        const __nv_bfloat16* sl = g_Wl + o * CIN + kc + half * 16;
        uint32_t dh = sbase + OFF_A + (buf * 2 + 0) * A_TILE + o * A_STRIDE + half * 32;
        uint32_t dl = sbase + OFF_A + (buf * 2 + 1) * A_TILE + o * A_STRIDE + half * 32;
        cpa16(dh, sh); cpa16(dh + 16, sh + 8);
        cpa16(dl, sl); cpa16(dl + 16, sl + 8);
    };
    auto issueB = [&](int kc, int buf) {
        int c = tid >> 3, seg = tid & 7;
        size_t so = (size_t)(b * CIN + kc + c) * VPAD + v0 + seg * 16;
        uint32_t dh = sbase + OFF_B + (buf * 2 + 0) * B_TILE + c * B_STRIDE + seg * 32;
        uint32_t dl = sbase + OFF_B + (buf * 2 + 1) * B_TILE + c * B_STRIDE + seg * 32;
        cpa16(dh, g_xh + so); cpa16(dh + 16, g_xh + so + 8);
        cpa16(dl, g_xl + so); cpa16(dl + 16, g_xl + so + 8);
    };

    // ---- compute one BK=32 chunk from smem[buf] (layout identical to R4) ----
    const int arow   = lane & 15;
    const int acol16 = (lane >> 4) * 16;
    const int brow   = ((lane >> 3) & 1) * 8 + (lane & 7);
    const int bcol16 = (lane >> 4) * 16;

    auto compute = [&](int buf) {
        #pragma unroll
        for (int combo = 0; combo < 3; combo++) {
            int sa = combo >> 1;   // 0,0,1
            int sx = combo & 1;    // 0,1,0
            uint32_t abase = sbase + OFF_A + (buf * 2 + sa) * A_TILE
                           + (wo + arow) * A_STRIDE + acol16;
            uint32_t bbase = sbase + OFF_B + (buf * 2 + sx) * B_TILE
                           + brow * B_STRIDE + wv * 2 + bcol16;
            #pragma unroll
            for (int ks = 0; ks < 2; ks++) {
                uint32_t af[4][4];
                #pragma unroll
                for (int mi = 0; mi < 4; mi++)
                    ldsm4(af[mi], abase + mi * 16 * A_STRIDE + ks * 32);
                uint32_t bf[2][4];
                #pragma unroll
                for (int np = 0; np < 2; np++)
                    ldsm4t(bf[np], bbase + ks * 16 * B_STRIDE + np * 32);
                #pragma unroll
                for (int mi = 0; mi < 4; mi++)
                    #pragma unroll
                    for (int nj = 0; nj < 4; nj++)
                        mma_bf16(acc[mi][nj], af[mi],
                                 bf[nj >> 1][(nj & 1) * 2],
                                 bf[nj >> 1][(nj & 1) * 2 + 1]);
            }
        }
    };

    // ---- pipeline: 2-stage cp.async ----
    issueA(0, 0); issueB(0, 0); CP_COMMIT();

    for (int kt = 0; kt < NKCH; kt++) {
        int buf = kt & 1;
        if (kt + 1 < NKCH) {
            issueA((kt + 1) * BK, buf ^ 1);
            issueB((kt + 1) * BK, buf ^ 1);
            CP_COMMIT();
            CP_WAIT(1);          // chunk kt complete, kt+1 in flight
        } else {
            CP_WAIT(0);
        }
        __syncthreads();         // copies visible to all threads
        compute(buf);
        __syncthreads();         // compute done before buf is overwritten
    }

    // ---- epilogue: acc + bias -> g_h ----
    #pragma unroll
    for (int mi = 0; mi < 4; mi++) {
        int o0 = wo + mi * 16 + (lane >> 2);
        float b0 = __ldg(&bias[o0]);
        float b1 = __ldg(&bias[o0 + 8]);
        float* h0 = g_h + ((size_t)b * COUT + o0) * VRAW;
        float* h1 = h0 + (size_t)8 * VRAW;
        #pragma unroll
        for (int nj = 0; nj < 4; nj++) {
            int gv = v0 + wv + nj * 8 + (lane & 3) * 2;
            if (gv < VRAW) {
                *(float2*)(h0 + gv) = make_float2(acc[mi][nj][0] + b0,
                                                  acc[mi][nj][1] + b0);
                *(float2*)(h1 + gv) = make_float2(acc[mi][nj][2] + b1,
                                                  acc[mi][nj][3] + b1);
            }
        }
    }
}

// ---------------------------------------------------------------------------
// Kernel 3: per-row scatter with last-write-wins (max v) duplicate semantics.
// ---------------------------------------------------------------------------
__global__ __launch_bounds__(1024, 1) void scatter_kernel(
    const int* __restrict__ mpi, float* __restrict__ y)
{
    extern __shared__ int win[];      // NVERT ints = 160.0 KB
    int row = blockIdx.x;             // b*COUT + o
    int tid = threadIdx.x;

    for (int j = tid; j < NVERT; j += 1024) win[j] = -1;
    __syncthreads();

    const int* mrow = mpi + (size_t)row * VRAW;
    #pragma unroll
    for (int i = 0; i < 11; i++) {
        int v = tid + (i << 10);
        if (v < VRAW) {
            int k = __ldg(&mrow[v]);               // value in [0,7)
            int vert = g_nd[(v << 3) + k];         // L2-resident table
            atomicMax(&win[vert], v);              // last write (max v) wins
        }
    }
    __syncthreads();

    const float* hrow = g_h + (size_t)row * VRAW;
    float* yrow = y + (size_t)row * NVERT;
    for (int j = tid; j < NVERT; j += 1024) {
        int w = win[j];
        yrow[j] = (w >= 0) ? __ldg(&hrow[w]) : 0.f;
    }
}

// ---------------------------------------------------------------------------
extern "C" void kernel_launch(void* const* d_in, const int* in_sizes, int n_in,
                              void* d_out, int out_size)
{
    const float* x    = (const float*)d_in[0];
    const float* W    = (const float*)d_in[1];
    const float* bias = (const float*)d_in[2];
    const int*   up   = (const int*)d_in[3];
    const int*   down = (const int*)d_in[4];
    const int*   mpi  = (const int*)d_in[5];
    float* y = (float*)d_out;

    cudaFuncSetAttribute(scatter_kernel,
                         cudaFuncAttributeMaxDynamicSharedMemorySize,
                         NVERT * (int)sizeof(int));
    cudaFuncSetAttribute(gemm_mma_kernel,
                         cudaFuncAttributeMaxDynamicSharedMemorySize,
                         SMEM_TOTAL);

    convert_x_kernel<<<(NB * CIN * NSEG + 255) / 256, 256>>>(x);
    convert_w_kernel<<<(COUT * CIN / 8 + 255) / 256, 256>>>(W);
    prep_nd_kernel<<<(VRAW * 8 + 255) / 256, 256>>>(up, down);

    dim3 g(NVB, NB);   // 81 x 16
    gemm_mma_kernel<<<g, 256, SMEM_TOTAL>>>(bias);

    scatter_kernel<<<NB * COUT, 1024, NVERT * (int)sizeof(int)>>>(mpi, y);
}